// round 2
// baseline (speedup 1.0000x reference)
#include <cuda_runtime.h>
#include <math.h>

#define BB   2048
#define NN   65536
#define PDIM 512
#define TDIM 256
#define CDIM 768
#define HDIM 64
#define RDIM 128
#define KK   16

// ---------------- scratch (device globals; no allocations) ----------------
__device__ float g_q[BB * RDIM];              // 1 MB  normalized queries
__device__ float g_k[NN * RDIM];              // 32 MB normalized keys
__device__ float g_sim[(size_t)BB * NN];      // 512 MB similarity matrix
__device__ int   g_topidx[BB * KK];
__device__ float g_r[BB * RDIM];
__device__ int   g_hasvalid[BB];

// output layout (floats)
#define OUT_TS (BB * PDIM)             // top_sim after z_tilde
#define OUT_TI (OUT_TS + BB * KK)      // top_idx
#define OUT_AL (OUT_TI + BB * KK)      // alpha

// =====================================================================
// Kernel 1/2: projection + L2 normalize.  out[row] = l2norm(cat(z,g) @ W^T + b)
// BT rows per block, 256 threads: tid -> (r = tid&127, grp = tid>>7), each
// (r,grp) computes BT/2 rows' outputs for column r.
// =====================================================================
template <int BT>
__global__ void __launch_bounds__(256) proj_norm_kernel(
    const float* __restrict__ zin, const float* __restrict__ gin,
    const float* __restrict__ W, const float* __restrict__ bias,
    float* __restrict__ outp)
{
    extern __shared__ float sm[];
    float* cat = sm;                         // [BT][CDIM]
    float* qt  = cat + BT * CDIM;            // [BT][RDIM]
    float* red = qt + BT * RDIM;             // [256]
    float* inv = red + 256;                  // [BT]

    const int tid  = threadIdx.x;
    const int row0 = blockIdx.x * BT;

    for (int e = tid; e < BT * PDIM; e += 256) {
        int b = e / PDIM, d = e - b * PDIM;
        cat[b * CDIM + d] = zin[(size_t)(row0 + b) * PDIM + d];
    }
    for (int e = tid; e < BT * TDIM; e += 256) {
        int b = e / TDIM, d = e - b * TDIM;
        cat[b * CDIM + PDIM + d] = gin[(size_t)(row0 + b) * TDIM + d];
    }
    __syncthreads();

    const int r   = tid & 127;
    const int grp = tid >> 7;          // 0..1
    const int RPG = BT / 2;
    const int b0  = grp * RPG;

    float acc[BT / 2];
    float bv = bias[r];
#pragma unroll
    for (int j = 0; j < RPG; j++) acc[j] = bv;

    const float4* W4   = (const float4*)(W + (size_t)r * CDIM);
    const float4* cat4 = (const float4*)cat;
    for (int d4 = 0; d4 < CDIM / 4; d4++) {
        float4 w = W4[d4];
#pragma unroll
        for (int j = 0; j < RPG; j++) {
            float4 c = cat4[(b0 + j) * (CDIM / 4) + d4];
            acc[j] += w.x * c.x + w.y * c.y + w.z * c.z + w.w * c.w;
        }
    }
#pragma unroll
    for (int j = 0; j < RPG; j++) qt[(b0 + j) * RDIM + r] = acc[j];
    __syncthreads();

    // row norms
    const int SEGS = 256 / BT, L = RDIM / SEGS;
    {
        int b = tid / SEGS, s = tid - b * SEGS;
        float ss = 0.f;
        for (int i = 0; i < L; i++) {
            float v = qt[b * RDIM + s * L + i];
            ss += v * v;
        }
        red[b * SEGS + s] = ss;
    }
    __syncthreads();
    if (tid < BT) {
        float ss = 0.f;
        for (int s = 0; s < SEGS; s++) ss += red[tid * SEGS + s];
        float n = sqrtf(ss);
        inv[tid] = 1.0f / fmaxf(n, 1e-12f);
    }
    __syncthreads();
    for (int e = tid; e < BT * RDIM; e += 256) {
        int b = e >> 7;
        outp[(size_t)(row0 + b) * RDIM + (e & 127)] = qt[e] * inv[b];
    }
}

// =====================================================================
// Kernel 3: sim = q @ k^T  (fp32).  Block = 64 queries x 128 keys.
// k tile stored XOR-swizzled (float4 granularity) for conflict-free LDS.
// Thread microtile 4q x 8k, float4 over d.
// =====================================================================
__global__ void __launch_bounds__(256) sim_kernel(float* __restrict__ sim)
{
    extern __shared__ float smem[];
    float*  qs  = smem;                       // [64][132] padded
    float4* qs4 = (float4*)qs;                // row stride 33 float4
    float4* ks4 = (float4*)(smem + 64 * 132); // [128][32] swizzled

    const int tid = threadIdx.x;
    const int kt  = blockIdx.x;               // key tile (128 keys)
    const int qt  = blockIdx.y;               // query tile (64 queries)

    // load q tile (coalesced; write float4 into padded rows)
    {
        int c4 = tid & 31, r0 = tid >> 5;
        const float4* gq4 = (const float4*)g_q;
        for (int rr = r0; rr < 64; rr += 8) {
            float4 v = gq4[(size_t)(qt * 64 + rr) * 32 + c4];
            *(float4*)&qs[rr * 132 + c4 * 4] = v;
        }
    }
    // load k tile with XOR swizzle
    {
        int c4 = tid & 31, r0 = tid >> 5;
        const float4* gk4 = (const float4*)g_k;
        for (int rr = r0; rr < 128; rr += 8) {
            float4 v = gk4[(size_t)(kt * 128 + rr) * 32 + c4];
            ks4[rr * 32 + (c4 ^ (rr & 7))] = v;
        }
    }
    __syncthreads();

    const int tx = tid & 15;   // key group (8 keys, interleaved stride 16)
    const int ty = tid >> 4;   // query group (4 queries)
    const int sw = tx & 7;

    float acc[4][8];
#pragma unroll
    for (int j = 0; j < 4; j++)
#pragma unroll
        for (int m = 0; m < 8; m++) acc[j][m] = 0.f;

#pragma unroll 4
    for (int d4 = 0; d4 < 32; d4++) {
        float4 qv[4];
#pragma unroll
        for (int j = 0; j < 4; j++) qv[j] = qs4[(ty * 4 + j) * 33 + d4];
#pragma unroll
        for (int m = 0; m < 8; m++) {
            float4 kv = ks4[(tx + 16 * m) * 32 + (d4 ^ sw)];
#pragma unroll
            for (int j = 0; j < 4; j++)
                acc[j][m] += qv[j].x * kv.x + qv[j].y * kv.y +
                             qv[j].z * kv.z + qv[j].w * kv.w;
        }
    }

#pragma unroll
    for (int j = 0; j < 4; j++) {
        size_t base = (size_t)(qt * 64 + ty * 4 + j) * NN + (size_t)kt * 128;
#pragma unroll
        for (int m = 0; m < 8; m++)
            sim[base + tx + 16 * m] = acc[j][m];
    }
}

// =====================================================================
// Kernel 4: masked top-16 per row (jax tie-break: lower index first),
// has_valid, writes top_sim / top_idx outputs.
// =====================================================================
__global__ void __launch_bounds__(256) topk_kernel(
    const unsigned int* __restrict__ mask, float* __restrict__ out)
{
    __shared__ float sv[4096];
    __shared__ int   si[4096];
    __shared__ float rv[256];
    __shared__ int   ri[256];
    __shared__ int   rp[256];
    __shared__ int   anyv[256];
    __shared__ float wv[16];
    __shared__ int   wi[16];

    const int b = blockIdx.x, tid = threadIdx.x;
    const float* srow = g_sim + (size_t)b * NN;
    const unsigned int* mrow = mask + (size_t)b * NN;

    float lv[16]; int li[16];
#pragma unroll
    for (int j = 0; j < 16; j++) { lv[j] = -INFINITY; li[j] = 0x7fffffff; }
    int hv = 0;

    for (int n = tid; n < NN; n += 256) {
        unsigned int m = mrow[n];
        hv |= (m != 0u);
        float v = (m != 0u) ? srow[n] : -1e9f;
        if (v > lv[15] || (v == lv[15] && n < li[15])) {
            float cv = v; int ci = n;
#pragma unroll
            for (int j = 0; j < 16; j++) {
                bool better = (cv > lv[j]) || (cv == lv[j] && ci < li[j]);
                float tv = lv[j]; int ti = li[j];
                if (better) { lv[j] = cv; li[j] = ci; cv = tv; ci = ti; }
            }
        }
    }
#pragma unroll
    for (int j = 0; j < 16; j++) { sv[tid * 16 + j] = lv[j]; si[tid * 16 + j] = li[j]; }
    anyv[tid] = hv;
    __syncthreads();
    for (int s = 128; s > 0; s >>= 1) {
        if (tid < s) anyv[tid] |= anyv[tid + s];
        __syncthreads();
    }

    int p = 0;  // my head pointer into my sorted 16-list
    for (int r = 0; r < 16; r++) {
        float v = (p < 16) ? sv[tid * 16 + p] : -INFINITY;
        int   i = (p < 16) ? si[tid * 16 + p] : 0x7fffffff;
        rv[tid] = v; ri[tid] = i; rp[tid] = tid;
        __syncthreads();
        for (int s = 128; s > 0; s >>= 1) {
            if (tid < s) {
                float v2 = rv[tid + s]; int i2 = ri[tid + s];
                if (v2 > rv[tid] || (v2 == rv[tid] && i2 < ri[tid])) {
                    rv[tid] = v2; ri[tid] = i2; rp[tid] = rp[tid + s];
                }
            }
            __syncthreads();
        }
        if (tid == 0) { wv[r] = rv[0]; wi[r] = ri[0]; }
        int owner = rp[0];
        __syncthreads();
        if (tid == owner) p++;
        __syncthreads();
    }

    if (tid < 16) {
        out[OUT_TS + b * 16 + tid] = wv[tid];
        out[OUT_TI + b * 16 + tid] = (float)wi[tid];
        g_topidx[b * 16 + tid] = wi[tid];
    }
    if (tid == 0) g_hasvalid[b] = anyv[0];
}

// =====================================================================
// Kernel 5: per-row attention stack: gather y, 2-layer MLP, compat MLP,
// softmax -> alpha (output), r_i (scratch).  128 threads per row.
// =====================================================================
__global__ void __launch_bounds__(128) attn_kernel(
    const float* __restrict__ bank_y,
    const float* __restrict__ Ws1, const float* __restrict__ bs1,
    const float* __restrict__ Ws2, const float* __restrict__ bs2,
    const float* __restrict__ Wc1, const float* __restrict__ bc1,
    const float* __restrict__ Wc2, const float* __restrict__ bc2,
    float* __restrict__ out)
{
    __shared__ float y[16][64];
    __shared__ float hbuf[16][128];
    __shared__ float proj[16][128];
    __shared__ float qv[128];
    __shared__ float cmat[128 * 16];
    __shared__ float tred[8 * 16];
    __shared__ float lg[16];
    __shared__ float alpha[16];
    __shared__ int   tix[16];

    const int b = blockIdx.x, tid = threadIdx.x;
    if (tid < 16) tix[tid] = g_topidx[b * 16 + tid];
    qv[tid] = g_q[(size_t)b * 128 + tid];
    __syncthreads();

    for (int e = tid; e < 16 * 64; e += 128)
        y[e >> 6][e & 63] = bank_y[(size_t)tix[e >> 6] * 64 + (e & 63)];
    __syncthreads();

    const int r = tid;
    // h = relu(y @ Ws1^T + bs1)    [16][128]
    {
        float4 w[16];
        const float4* W4 = (const float4*)(Ws1 + (size_t)r * 64);
#pragma unroll
        for (int i = 0; i < 16; i++) w[i] = W4[i];
        float bv = bs1[r];
        for (int j = 0; j < 16; j++) {
            float s = bv;
#pragma unroll
            for (int i = 0; i < 16; i++) {
                float4 yy = *(const float4*)&y[j][i * 4];
                s += w[i].x * yy.x + w[i].y * yy.y + w[i].z * yy.z + w[i].w * yy.w;
            }
            hbuf[j][r] = fmaxf(s, 0.f);
        }
    }
    __syncthreads();
    // proj = h @ Ws2^T + bs2       [16][128]
    {
        float accp[16];
        float bv = bs2[r];
#pragma unroll
        for (int j = 0; j < 16; j++) accp[j] = bv;
        const float4* W4 = (const float4*)(Ws2 + (size_t)r * 128);
        for (int i = 0; i < 32; i++) {
            float4 w = W4[i];
#pragma unroll
            for (int j = 0; j < 16; j++) {
                float4 hh = *(const float4*)&hbuf[j][i * 4];
                accp[j] += w.x * hh.x + w.y * hh.y + w.z * hh.z + w.w * hh.w;
            }
        }
#pragma unroll
        for (int j = 0; j < 16; j++) proj[j][r] = accp[j];
    }
    __syncthreads();

    // logits: tanh([q,proj] @ Wc1^T + bc1) @ Wc2^T + bc2
    {
        float uqr = bc1[r];
        const float4* Wq4 = (const float4*)(Wc1 + (size_t)r * 256);
        for (int i = 0; i < 32; i++) {
            float4 w = Wq4[i];
            float4 qq = *(const float4*)&qv[i * 4];
            uqr += w.x * qq.x + w.y * qq.y + w.z * qq.z + w.w * qq.w;
        }
        float sacc[16];
#pragma unroll
        for (int j = 0; j < 16; j++) sacc[j] = uqr;
        const float4* Wp4 = (const float4*)(Wc1 + (size_t)r * 256 + 128);
        for (int i = 0; i < 32; i++) {
            float4 w = Wp4[i];
#pragma unroll
            for (int j = 0; j < 16; j++) {
                float4 pp = *(const float4*)&proj[j][i * 4];
                sacc[j] += w.x * pp.x + w.y * pp.y + w.z * pp.z + w.w * pp.w;
            }
        }
        float w2r = Wc2[r];
#pragma unroll
        for (int j = 0; j < 16; j++) cmat[r * 16 + j] = tanhf(sacc[j]) * w2r;
    }
    __syncthreads();
    {
        int j = tid & 15, c = tid >> 4;  // 8 chunks of 16 rows
        float s = 0.f;
        for (int i = 0; i < 16; i++) s += cmat[(c * 16 + i) * 16 + j];
        tred[c * 16 + j] = s;
    }
    __syncthreads();
    if (tid < 16) {
        float s = bc2[0];
        for (int c = 0; c < 8; c++) s += tred[c * 16 + tid];
        lg[tid] = s;
    }
    __syncthreads();
    if (tid == 0) {
        if (g_hasvalid[b]) {
            float mx = lg[0];
            for (int j = 1; j < 16; j++) mx = fmaxf(mx, lg[j]);
            float se = 0.f, ev[16];
            for (int j = 0; j < 16; j++) { ev[j] = expf(lg[j] - mx); se += ev[j]; }
            float isv = 1.0f / se;
            for (int j = 0; j < 16; j++) alpha[j] = ev[j] * isv;
        } else {
            for (int j = 0; j < 16; j++) alpha[j] = 0.f;
        }
    }
    __syncthreads();
    if (tid < 16) out[OUT_AL + b * 16 + tid] = alpha[tid];
    {
        float s = 0.f;
#pragma unroll
        for (int j = 0; j < 16; j++) s += alpha[j] * proj[j][tid];
        g_r[(size_t)b * 128 + tid] = s;
    }
}

// =====================================================================
// Kernel 6: z_tilde = has_valid ? relu([z,r] @ Wa^T + ba) : z.
// 16 rows per block, 256 threads, each thread owns 2 output cols.
// =====================================================================
__global__ void __launch_bounds__(256) aug_kernel(
    const float* __restrict__ zin, const float* __restrict__ Wa,
    const float* __restrict__ ba, float* __restrict__ out)
{
    __shared__ float zr[16 * 640];
    __shared__ int   hv[16];
    const int tid = threadIdx.x, b0 = blockIdx.x * 16;

    for (int e = tid; e < 16 * PDIM; e += 256) {
        int j = e / PDIM, d = e - j * PDIM;
        zr[j * 640 + d] = zin[(size_t)(b0 + j) * PDIM + d];
    }
    for (int e = tid; e < 16 * RDIM; e += 256) {
        int j = e >> 7, d = e & 127;
        zr[j * 640 + PDIM + d] = g_r[(size_t)(b0 + j) * RDIM + d];
    }
    if (tid < 16) hv[tid] = g_hasvalid[b0 + tid];
    __syncthreads();

    for (int half = 0; half < 2; half++) {
        int o = tid + half * 256;
        float acc[16];
        float bv = ba[o];
#pragma unroll
        for (int j = 0; j < 16; j++) acc[j] = bv;
        const float4* W4 = (const float4*)(Wa + (size_t)o * 640);
        for (int i = 0; i < 160; i++) {
            float4 w = W4[i];
#pragma unroll
            for (int j = 0; j < 16; j++) {
                float4 zz = *(const float4*)&zr[j * 640 + i * 4];
                acc[j] += w.x * zz.x + w.y * zz.y + w.z * zz.z + w.w * zz.w;
            }
        }
#pragma unroll
        for (int j = 0; j < 16; j++) {
            float v = hv[j] ? fmaxf(acc[j], 0.f) : zr[j * 640 + o];
            out[(size_t)(b0 + j) * PDIM + o] = v;
        }
    }
}

// =====================================================================
extern "C" void kernel_launch(void* const* d_in, const int* in_sizes, int n_in,
                              void* d_out, int out_size)
{
    const float* z_i    = (const float*)d_in[0];
    const float* g_i    = (const float*)d_in[1];
    const float* bank_z = (const float*)d_in[2];
    const float* bank_g = (const float*)d_in[3];
    const float* bank_y = (const float*)d_in[4];
    const unsigned int* vmask = (const unsigned int*)d_in[5];
    const float* Wq  = (const float*)d_in[6];
    const float* bq  = (const float*)d_in[7];
    const float* Wk  = (const float*)d_in[8];
    const float* bk  = (const float*)d_in[9];
    const float* Ws1 = (const float*)d_in[10];
    const float* bs1 = (const float*)d_in[11];
    const float* Ws2 = (const float*)d_in[12];
    const float* bs2 = (const float*)d_in[13];
    const float* Wc1 = (const float*)d_in[14];
    const float* bc1 = (const float*)d_in[15];
    const float* Wc2 = (const float*)d_in[16];
    const float* bc2 = (const float*)d_in[17];
    const float* Wa  = (const float*)d_in[18];
    const float* ba  = (const float*)d_in[19];
    float* out = (float*)d_out;

    float* pq; cudaGetSymbolAddress((void**)&pq, g_q);
    float* pk; cudaGetSymbolAddress((void**)&pk, g_k);
    float* ps; cudaGetSymbolAddress((void**)&ps, g_sim);

    const int smemQ = (16 * CDIM + 16 * RDIM + 256 + 16) * 4;
    const int smemK = (32 * CDIM + 32 * RDIM + 256 + 32) * 4;
    const int smemS = (64 * 132 + 128 * 32 * 4) * 4;

    cudaFuncSetAttribute(proj_norm_kernel<16>, cudaFuncAttributeMaxDynamicSharedMemorySize, smemQ);
    cudaFuncSetAttribute(proj_norm_kernel<32>, cudaFuncAttributeMaxDynamicSharedMemorySize, smemK);
    cudaFuncSetAttribute(sim_kernel, cudaFuncAttributeMaxDynamicSharedMemorySize, smemS);

    proj_norm_kernel<16><<<BB / 16, 256, smemQ>>>(z_i, g_i, Wq, bq, pq);
    proj_norm_kernel<32><<<NN / 32, 256, smemK>>>(bank_z, bank_g, Wk, bk, pk);
    sim_kernel<<<dim3(NN / 128, BB / 64), 256, smemS>>>(ps);
    topk_kernel<<<BB, 256>>>(vmask, out);
    attn_kernel<<<BB, 128>>>(bank_y, Ws1, bs1, Ws2, bs2, Wc1, bc1, Wc2, bc2, out);
    aug_kernel<<<BB / 16, 256>>>(z_i, Wa, ba, out);
}

// round 3
// speedup vs baseline: 1.6270x; 1.6270x over previous
#include <cuda_runtime.h>
#include <math.h>

#define BB   2048
#define NN   65536
#define PDIM 512
#define TDIM 256
#define CDIM 768
#define HDIM 64
#define RDIM 128
#define KK   16

// ---------------- scratch (device globals; no allocations) ----------------
__device__ float g_bcatT[CDIM * NN];          // 192 MB  bank concat, d-major
__device__ float g_qcatT[CDIM * BB];          // 6 MB    query concat, d-major
__device__ float g_WqT[CDIM * RDIM];          // WT layouts
__device__ float g_WkT[CDIM * RDIM];
__device__ float g_qT[RDIM * BB];             // 1 MB  normalized queries, d-major
__device__ float g_kT[RDIM * NN];             // 32 MB normalized keys, d-major
__device__ float g_sim[(size_t)BB * NN];      // 512 MB similarity
__device__ int   g_topidx[BB * KK];
__device__ float g_r[BB * RDIM];
__device__ int   g_hasvalid[BB];

// output layout (floats)
#define OUT_TS (BB * PDIM)
#define OUT_TI (OUT_TS + BB * KK)
#define OUT_AL (OUT_TI + BB * KK)

// =====================================================================
// Prep A: transpose Wq/Wk [128][768] -> WT [768][128]
// =====================================================================
__global__ void wT_kernel(const float* __restrict__ Wq, const float* __restrict__ Wk)
{
    __shared__ float t[32][33];
    const float* src = blockIdx.z ? Wk : Wq;
    float* dst = blockIdx.z ? g_WkT : g_WqT;
    int c0 = blockIdx.x * 32;   // in-dim (768)
    int r0 = blockIdx.y * 32;   // out-dim (128)
#pragma unroll
    for (int i = 0; i < 4; i++)
        t[threadIdx.y + i * 8][threadIdx.x] = src[(size_t)(r0 + threadIdx.y + i * 8) * CDIM + c0 + threadIdx.x];
    __syncthreads();
#pragma unroll
    for (int i = 0; i < 4; i++)
        dst[(size_t)(c0 + threadIdx.y + i * 8) * RDIM + r0 + threadIdx.x] = t[threadIdx.x][threadIdx.y + i * 8];
}

// =====================================================================
// Prep B: concat+transpose  (rows x [z|g])  ->  catT [768][NR]
// =====================================================================
__global__ void catT_kernel(const float* __restrict__ z, const float* __restrict__ g,
                            float* __restrict__ catT, int NR)
{
    __shared__ float t[32][33];
    int n0 = blockIdx.x * 32;
    int d0 = blockIdx.y * 32;
#pragma unroll
    for (int i = 0; i < 4; i++) {
        int n = n0 + threadIdx.y + i * 8;
        int d = d0 + threadIdx.x;
        float v = (d0 < PDIM) ? z[(size_t)n * PDIM + d]
                              : g[(size_t)n * TDIM + (d - PDIM)];
        t[threadIdx.y + i * 8][threadIdx.x] = v;
    }
    __syncthreads();
#pragma unroll
    for (int i = 0; i < 4; i++)
        catT[(size_t)(d0 + threadIdx.y + i * 8) * NR + n0 + threadIdx.x] = t[threadIdx.x][threadIdx.y + i * 8];
}

// =====================================================================
// Proj GEMM + L2 norm:  outT[d][row] = l2norm_row( catT^T @ WT + b )
// Block: 128 rows x 128 out-cols, 256 threads, 8x8 microtile, 24 k-tiles of 32.
// =====================================================================
__global__ void __launch_bounds__(256, 1) proj_gemm_kernel(
    const float* __restrict__ catT, const float* __restrict__ WT,
    const float* __restrict__ bias, float* __restrict__ outT, int NR)
{
    extern __shared__ float dyn[];
    float* is = dyn;            // [32][128]
    float* ws = dyn + 4096;     // [32][128]
    __shared__ float invs[128];

    const int tid = threadIdx.x;
    const int tx = tid & 15;    // col group
    const int ty = tid >> 4;    // row group
    const int row0 = blockIdx.x * 128;

    float acc[8][8];
#pragma unroll
    for (int m = 0; m < 8; m++) {
        float bv = bias[tx * 8 + m];
#pragma unroll
        for (int j = 0; j < 8; j++) acc[j][m] = bv;
    }

    for (int kt = 0; kt < 24; kt++) {
#pragma unroll
        for (int it = 0; it < 4; it++) {
            int idx = tid + it * 256;        // 0..1023 float4 slots
            int dd = idx >> 5, c4 = idx & 31;
            *(float4*)&is[dd * 128 + c4 * 4] =
                *(const float4*)&catT[(size_t)(kt * 32 + dd) * NR + row0 + c4 * 4];
            *(float4*)&ws[dd * 128 + c4 * 4] =
                *(const float4*)&WT[(size_t)(kt * 32 + dd) * RDIM + c4 * 4];
        }
        __syncthreads();
#pragma unroll 4
        for (int dd = 0; dd < 32; dd++) {
            float a[8], b[8];
            *(float4*)&a[0] = *(float4*)&is[dd * 128 + ty * 8];
            *(float4*)&a[4] = *(float4*)&is[dd * 128 + ty * 8 + 4];
            *(float4*)&b[0] = *(float4*)&ws[dd * 128 + tx * 8];
            *(float4*)&b[4] = *(float4*)&ws[dd * 128 + tx * 8 + 4];
#pragma unroll
            for (int j = 0; j < 8; j++)
#pragma unroll
                for (int m = 0; m < 8; m++)
                    acc[j][m] += a[j] * b[m];
        }
        __syncthreads();
    }

    // row sum-of-squares reduction across the 16 tx groups
    float* red = dyn;   // [128][16]
#pragma unroll
    for (int j = 0; j < 8; j++) {
        float p = 0.f;
#pragma unroll
        for (int m = 0; m < 8; m++) p += acc[j][m] * acc[j][m];
        red[(ty * 8 + j) * 16 + tx] = p;
    }
    __syncthreads();
    if (tid < 128) {
        float ss = 0.f;
#pragma unroll
        for (int t = 0; t < 16; t++) ss += red[tid * 16 + t];
        invs[tid] = 1.0f / fmaxf(sqrtf(ss), 1e-12f);
    }
    __syncthreads();

    // stage transposed output in smem, then coalesced write
    float* os = dyn;    // [128 col][129]
#pragma unroll
    for (int j = 0; j < 8; j++) {
        float iv = invs[ty * 8 + j];
#pragma unroll
        for (int m = 0; m < 8; m++)
            os[(tx * 8 + m) * 129 + ty * 8 + j] = acc[j][m] * iv;
    }
    __syncthreads();
    for (int it = 0; it < 64; it++) {
        int idx = tid + it * 256;
        int col = idx >> 7, r = idx & 127;
        outT[(size_t)col * NR + row0 + r] = os[col * 129 + r];
    }
}

// =====================================================================
// sim = q @ k^T.  Block = 128q x 128k, full d=128 staged once (128 KB smem).
// 8x8 microtile, conflict-free (both operands d-major).
// =====================================================================
__global__ void __launch_bounds__(256, 1) sim_kernel(float* __restrict__ sim)
{
    extern __shared__ float smem[];
    float* qs = smem;            // [128 d][128 q]
    float* ks = smem + 16384;    // [128 d][128 k]

    const int tid = threadIdx.x;
    const int kt = blockIdx.x;
    const int qt = blockIdx.y;

#pragma unroll
    for (int it = 0; it < 16; it++) {
        int idx = tid + it * 256;          // 4096 float4 slots per tile
        int d = idx >> 5, c4 = idx & 31;
        *(float4*)&qs[d * 128 + c4 * 4] =
            *(const float4*)&g_qT[(size_t)d * BB + qt * 128 + c4 * 4];
        *(float4*)&ks[d * 128 + c4 * 4] =
            *(const float4*)&g_kT[(size_t)d * NN + (size_t)kt * 128 + c4 * 4];
    }
    __syncthreads();

    const int tx = tid & 15;   // k group
    const int ty = tid >> 4;   // q group

    float acc[8][8];
#pragma unroll
    for (int j = 0; j < 8; j++)
#pragma unroll
        for (int m = 0; m < 8; m++) acc[j][m] = 0.f;

#pragma unroll 4
    for (int d = 0; d < 128; d++) {
        float a[8], b[8];
        *(float4*)&a[0] = *(float4*)&qs[d * 128 + ty * 8];
        *(float4*)&a[4] = *(float4*)&qs[d * 128 + ty * 8 + 4];
        *(float4*)&b[0] = *(float4*)&ks[d * 128 + tx * 8];
        *(float4*)&b[4] = *(float4*)&ks[d * 128 + tx * 8 + 4];
#pragma unroll
        for (int j = 0; j < 8; j++)
#pragma unroll
            for (int m = 0; m < 8; m++)
                acc[j][m] += a[j] * b[m];
    }

#pragma unroll
    for (int j = 0; j < 8; j++) {
        size_t base = (size_t)(qt * 128 + ty * 8 + j) * NN + (size_t)kt * 128 + tx * 8;
        float4 v0 = make_float4(acc[j][0], acc[j][1], acc[j][2], acc[j][3]);
        float4 v1 = make_float4(acc[j][4], acc[j][5], acc[j][6], acc[j][7]);
        *(float4*)&sim[base] = v0;
        *(float4*)&sim[base + 4] = v1;
    }
}

// =====================================================================
// masked top-16 per row (jax tie-break: lower index first)
// =====================================================================
__device__ __forceinline__ void topk_push(float v, int n, float* lv, int* li)
{
    if (v > lv[15] || (v == lv[15] && n < li[15])) {
        float cv = v; int ci = n;
#pragma unroll
        for (int j = 0; j < 16; j++) {
            bool better = (cv > lv[j]) || (cv == lv[j] && ci < li[j]);
            float tv = lv[j]; int ti = li[j];
            if (better) { lv[j] = cv; li[j] = ci; cv = tv; ci = ti; }
        }
    }
}

__global__ void __launch_bounds__(256) topk_kernel(
    const unsigned int* __restrict__ mask, float* __restrict__ out)
{
    __shared__ float sv[4096];
    __shared__ int   si[4096];
    __shared__ float rv[256];
    __shared__ int   ri[256];
    __shared__ int   rp[256];
    __shared__ int   anyv[256];
    __shared__ float wv[16];
    __shared__ int   wi[16];

    const int b = blockIdx.x, tid = threadIdx.x;
    const float4* s4 = (const float4*)(g_sim + (size_t)b * NN);
    const uint4*  m4 = (const uint4*)(mask + (size_t)b * NN);

    float lv[16]; int li[16];
#pragma unroll
    for (int j = 0; j < 16; j++) { lv[j] = -INFINITY; li[j] = 0x7fffffff; }
    unsigned int hv = 0;

    for (int n4 = tid; n4 < NN / 4; n4 += 256) {
        float4 v4 = s4[n4];
        uint4  mm = m4[n4];
        hv |= (mm.x | mm.y | mm.z | mm.w);
        int n = n4 * 4;
        topk_push(mm.x ? v4.x : -1e9f, n + 0, lv, li);
        topk_push(mm.y ? v4.y : -1e9f, n + 1, lv, li);
        topk_push(mm.z ? v4.z : -1e9f, n + 2, lv, li);
        topk_push(mm.w ? v4.w : -1e9f, n + 3, lv, li);
    }
#pragma unroll
    for (int j = 0; j < 16; j++) { sv[tid * 16 + j] = lv[j]; si[tid * 16 + j] = li[j]; }
    anyv[tid] = (hv != 0u);
    __syncthreads();
    for (int s = 128; s > 0; s >>= 1) {
        if (tid < s) anyv[tid] |= anyv[tid + s];
        __syncthreads();
    }

    int p = 0;
    for (int r = 0; r < 16; r++) {
        float v = (p < 16) ? sv[tid * 16 + p] : -INFINITY;
        int   i = (p < 16) ? si[tid * 16 + p] : 0x7fffffff;
        rv[tid] = v; ri[tid] = i; rp[tid] = tid;
        __syncthreads();
        for (int s = 128; s > 0; s >>= 1) {
            if (tid < s) {
                float v2 = rv[tid + s]; int i2 = ri[tid + s];
                if (v2 > rv[tid] || (v2 == rv[tid] && i2 < ri[tid])) {
                    rv[tid] = v2; ri[tid] = i2; rp[tid] = rp[tid + s];
                }
            }
            __syncthreads();
        }
        if (tid == 0) { wv[r] = rv[0]; wi[r] = ri[0]; }
        int owner = rp[0];
        __syncthreads();
        if (tid == owner) p++;
        __syncthreads();
    }

    if (tid < 16) {
        out[OUT_TS + b * 16 + tid] = wv[tid];
        out[OUT_TI + b * 16 + tid] = (float)wi[tid];
        g_topidx[b * 16 + tid] = wi[tid];
    }
    if (tid == 0) g_hasvalid[b] = anyv[0];
}

// =====================================================================
// per-row attention stack
// =====================================================================
__global__ void __launch_bounds__(128) attn_kernel(
    const float* __restrict__ bank_y,
    const float* __restrict__ Ws1, const float* __restrict__ bs1,
    const float* __restrict__ Ws2, const float* __restrict__ bs2,
    const float* __restrict__ Wc1, const float* __restrict__ bc1,
    const float* __restrict__ Wc2, const float* __restrict__ bc2,
    float* __restrict__ out)
{
    __shared__ float y[16][64];
    __shared__ float hbuf[16][128];
    __shared__ float proj[16][128];
    __shared__ float qv[128];
    __shared__ float cmat[128 * 16];
    __shared__ float tred[8 * 16];
    __shared__ float lg[16];
    __shared__ float alpha[16];
    __shared__ int   tix[16];

    const int b = blockIdx.x, tid = threadIdx.x;
    if (tid < 16) tix[tid] = g_topidx[b * 16 + tid];
    qv[tid] = g_qT[(size_t)tid * BB + b];
    __syncthreads();

    for (int e = tid; e < 16 * 64; e += 128)
        y[e >> 6][e & 63] = bank_y[(size_t)tix[e >> 6] * 64 + (e & 63)];
    __syncthreads();

    const int r = tid;
    {
        float4 w[16];
        const float4* W4 = (const float4*)(Ws1 + (size_t)r * 64);
#pragma unroll
        for (int i = 0; i < 16; i++) w[i] = W4[i];
        float bv = bs1[r];
        for (int j = 0; j < 16; j++) {
            float s = bv;
#pragma unroll
            for (int i = 0; i < 16; i++) {
                float4 yy = *(const float4*)&y[j][i * 4];
                s += w[i].x * yy.x + w[i].y * yy.y + w[i].z * yy.z + w[i].w * yy.w;
            }
            hbuf[j][r] = fmaxf(s, 0.f);
        }
    }
    __syncthreads();
    {
        float accp[16];
        float bv = bs2[r];
#pragma unroll
        for (int j = 0; j < 16; j++) accp[j] = bv;
        const float4* W4 = (const float4*)(Ws2 + (size_t)r * 128);
        for (int i = 0; i < 32; i++) {
            float4 w = W4[i];
#pragma unroll
            for (int j = 0; j < 16; j++) {
                float4 hh = *(const float4*)&hbuf[j][i * 4];
                accp[j] += w.x * hh.x + w.y * hh.y + w.z * hh.z + w.w * hh.w;
            }
        }
#pragma unroll
        for (int j = 0; j < 16; j++) proj[j][r] = accp[j];
    }
    __syncthreads();

    {
        float uqr = bc1[r];
        const float4* Wq4 = (const float4*)(Wc1 + (size_t)r * 256);
        for (int i = 0; i < 32; i++) {
            float4 w = Wq4[i];
            float4 qq = *(const float4*)&qv[i * 4];
            uqr += w.x * qq.x + w.y * qq.y + w.z * qq.z + w.w * qq.w;
        }
        float sacc[16];
#pragma unroll
        for (int j = 0; j < 16; j++) sacc[j] = uqr;
        const float4* Wp4 = (const float4*)(Wc1 + (size_t)r * 256 + 128);
        for (int i = 0; i < 32; i++) {
            float4 w = Wp4[i];
#pragma unroll
            for (int j = 0; j < 16; j++) {
                float4 pp = *(const float4*)&proj[j][i * 4];
                sacc[j] += w.x * pp.x + w.y * pp.y + w.z * pp.z + w.w * pp.w;
            }
        }
        float w2r = Wc2[r];
#pragma unroll
        for (int j = 0; j < 16; j++) cmat[r * 16 + j] = tanhf(sacc[j]) * w2r;
    }
    __syncthreads();
    {
        int j = tid & 15, c = tid >> 4;
        float s = 0.f;
        for (int i = 0; i < 16; i++) s += cmat[(c * 16 + i) * 16 + j];
        tred[c * 16 + j] = s;
    }
    __syncthreads();
    if (tid < 16) {
        float s = bc2[0];
        for (int c = 0; c < 8; c++) s += tred[c * 16 + tid];
        lg[tid] = s;
    }
    __syncthreads();
    if (tid == 0) {
        if (g_hasvalid[b]) {
            float mx = lg[0];
            for (int j = 1; j < 16; j++) mx = fmaxf(mx, lg[j]);
            float se = 0.f, ev[16];
            for (int j = 0; j < 16; j++) { ev[j] = expf(lg[j] - mx); se += ev[j]; }
            float isv = 1.0f / se;
            for (int j = 0; j < 16; j++) alpha[j] = ev[j] * isv;
        } else {
            for (int j = 0; j < 16; j++) alpha[j] = 0.f;
        }
    }
    __syncthreads();
    if (tid < 16) out[OUT_AL + b * 16 + tid] = alpha[tid];
    {
        float s = 0.f;
#pragma unroll
        for (int j = 0; j < 16; j++) s += alpha[j] * proj[j][tid];
        g_r[(size_t)b * 128 + tid] = s;
    }
}

// =====================================================================
// z_tilde = has_valid ? relu([z,r] @ Wa^T + ba) : z
// =====================================================================
__global__ void __launch_bounds__(256) aug_kernel(
    const float* __restrict__ zin, const float* __restrict__ Wa,
    const float* __restrict__ ba, float* __restrict__ out)
{
    __shared__ float zr[16 * 640];
    __shared__ int   hv[16];
    const int tid = threadIdx.x, b0 = blockIdx.x * 16;

    for (int e = tid; e < 16 * PDIM; e += 256) {
        int j = e / PDIM, d = e - j * PDIM;
        zr[j * 640 + d] = zin[(size_t)(b0 + j) * PDIM + d];
    }
    for (int e = tid; e < 16 * RDIM; e += 256) {
        int j = e >> 7, d = e & 127;
        zr[j * 640 + PDIM + d] = g_r[(size_t)(b0 + j) * RDIM + d];
    }
    if (tid < 16) hv[tid] = g_hasvalid[b0 + tid];
    __syncthreads();

    for (int half = 0; half < 2; half++) {
        int o = tid + half * 256;
        float acc[16];
        float bv = ba[o];
#pragma unroll
        for (int j = 0; j < 16; j++) acc[j] = bv;
        const float4* W4 = (const float4*)(Wa + (size_t)o * 640);
        for (int i = 0; i < 160; i++) {
            float4 w = W4[i];
#pragma unroll
            for (int j = 0; j < 16; j++) {
                float4 zz = *(const float4*)&zr[j * 640 + i * 4];
                acc[j] += w.x * zz.x + w.y * zz.y + w.z * zz.z + w.w * zz.w;
            }
        }
#pragma unroll
        for (int j = 0; j < 16; j++) {
            float v = hv[j] ? fmaxf(acc[j], 0.f) : zr[j * 640 + o];
            out[(size_t)(b0 + j) * PDIM + o] = v;
        }
    }
}

// =====================================================================
extern "C" void kernel_launch(void* const* d_in, const int* in_sizes, int n_in,
                              void* d_out, int out_size)
{
    const float* z_i    = (const float*)d_in[0];
    const float* g_i    = (const float*)d_in[1];
    const float* bank_z = (const float*)d_in[2];
    const float* bank_g = (const float*)d_in[3];
    const float* bank_y = (const float*)d_in[4];
    const unsigned int* vmask = (const unsigned int*)d_in[5];
    const float* Wq  = (const float*)d_in[6];
    const float* bq  = (const float*)d_in[7];
    const float* Wk  = (const float*)d_in[8];
    const float* bk  = (const float*)d_in[9];
    const float* Ws1 = (const float*)d_in[10];
    const float* bs1 = (const float*)d_in[11];
    const float* Ws2 = (const float*)d_in[12];
    const float* bs2 = (const float*)d_in[13];
    const float* Wc1 = (const float*)d_in[14];
    const float* bc1 = (const float*)d_in[15];
    const float* Wc2 = (const float*)d_in[16];
    const float* bc2 = (const float*)d_in[17];
    const float* Wa  = (const float*)d_in[18];
    const float* ba  = (const float*)d_in[19];
    float* out = (float*)d_out;

    float* p_bcatT; cudaGetSymbolAddress((void**)&p_bcatT, g_bcatT);
    float* p_qcatT; cudaGetSymbolAddress((void**)&p_qcatT, g_qcatT);
    float* p_WqT;   cudaGetSymbolAddress((void**)&p_WqT, g_WqT);
    float* p_WkT;   cudaGetSymbolAddress((void**)&p_WkT, g_WkT);
    float* p_qT;    cudaGetSymbolAddress((void**)&p_qT, g_qT);
    float* p_kT;    cudaGetSymbolAddress((void**)&p_kT, g_kT);
    float* p_sim;   cudaGetSymbolAddress((void**)&p_sim, g_sim);

    const int smemProj = 16512 * 4;    // os staging (128x129 floats)
    const int smemSim  = 32768 * 4;    // 128 KB: two 128x128 tiles

    static int attr_done = 0;
    if (!attr_done) {
        cudaFuncSetAttribute(proj_gemm_kernel, cudaFuncAttributeMaxDynamicSharedMemorySize, smemProj);
        cudaFuncSetAttribute(sim_kernel, cudaFuncAttributeMaxDynamicSharedMemorySize, smemSim);
        attr_done = 1;
    }

    wT_kernel<<<dim3(24, 4, 2), dim3(32, 8)>>>(Wq, Wk);
    catT_kernel<<<dim3(NN / 32, 24), dim3(32, 8)>>>(bank_z, bank_g, p_bcatT, NN);
    catT_kernel<<<dim3(BB / 32, 24), dim3(32, 8)>>>(z_i, g_i, p_qcatT, BB);

    proj_gemm_kernel<<<BB / 128, 256, smemProj>>>(p_qcatT, p_WqT, bq, p_qT, BB);
    proj_gemm_kernel<<<NN / 128, 256, smemProj>>>(p_bcatT, p_WkT, bk, p_kT, NN);

    sim_kernel<<<dim3(NN / 128, BB / 128), 256, smemSim>>>(p_sim);
    topk_kernel<<<BB, 256>>>(vmask, out);
    attn_kernel<<<BB, 128>>>(bank_y, Ws1, bs1, Ws2, bs2, Wc1, bc1, Wc2, bc2, out);
    aug_kernel<<<BB / 16, 256>>>(z_i, Wa, ba, out);
}

// round 5
// speedup vs baseline: 1.6331x; 1.0038x over previous
#include <cuda_runtime.h>
#include <math.h>

#define BB   2048
#define NN   65536
#define PDIM 512
#define TDIM 256
#define CDIM 768
#define HDIM 64
#define RDIM 128
#define KK   16

// ---------------- scratch (device globals; no allocations) ----------------
__device__ float g_bcatT[CDIM * NN];          // 192 MB  bank concat, d-major
__device__ float g_qcatT[CDIM * BB];          // 6 MB    query concat, d-major
__device__ float g_WqT[CDIM * RDIM];
__device__ float g_WkT[CDIM * RDIM];
__device__ float g_qT[RDIM * BB];             // normalized queries, d-major
__device__ float g_kT[RDIM * NN];             // normalized keys, d-major
__device__ float g_sim[(size_t)BB * NN];      // 512 MB similarity
__device__ int   g_topidx[BB * KK];
__device__ float g_r[BB * RDIM];
__device__ int   g_hasvalid[BB];

// output layout (floats)
#define OUT_TS (BB * PDIM)
#define OUT_TI (OUT_TS + BB * KK)
#define OUT_AL (OUT_TI + BB * KK)

// ---------------- packed fp32x2 FMA helpers ----------------
__device__ __forceinline__ unsigned long long pack2(float x, float y) {
    unsigned long long r;
    asm("mov.b64 %0, {%1, %2};" : "=l"(r) : "f"(x), "f"(y));
    return r;
}
__device__ __forceinline__ void unpack2(unsigned long long v, float& x, float& y) {
    asm("mov.b64 {%0, %1}, %2;" : "=f"(x), "=f"(y) : "l"(v));
}
__device__ __forceinline__ void ffma2(unsigned long long& d,
                                      unsigned long long a, unsigned long long b) {
    asm("fma.rn.f32x2 %0, %1, %2, %0;" : "+l"(d) : "l"(a), "l"(b));
}

// =====================================================================
// Prep A: transpose Wq/Wk [128][768] -> WT [768][128]
// =====================================================================
__global__ void wT_kernel(const float* __restrict__ Wq, const float* __restrict__ Wk)
{
    __shared__ float t[32][33];
    const float* src = blockIdx.z ? Wk : Wq;
    float* dst = blockIdx.z ? g_WkT : g_WqT;
    int c0 = blockIdx.x * 32;
    int r0 = blockIdx.y * 32;
#pragma unroll
    for (int i = 0; i < 4; i++)
        t[threadIdx.y + i * 8][threadIdx.x] = src[(size_t)(r0 + threadIdx.y + i * 8) * CDIM + c0 + threadIdx.x];
    __syncthreads();
#pragma unroll
    for (int i = 0; i < 4; i++)
        dst[(size_t)(c0 + threadIdx.y + i * 8) * RDIM + r0 + threadIdx.x] = t[threadIdx.x][threadIdx.y + i * 8];
}

// =====================================================================
// Prep B: concat+transpose  (rows x [z|g])  ->  catT [768][NR]
// =====================================================================
__global__ void catT_kernel(const float* __restrict__ z, const float* __restrict__ g,
                            float* __restrict__ catT, int NR)
{
    __shared__ float t[32][33];
    int n0 = blockIdx.x * 32;
    int d0 = blockIdx.y * 32;
#pragma unroll
    for (int i = 0; i < 4; i++) {
        int n = n0 + threadIdx.y + i * 8;
        int d = d0 + threadIdx.x;
        float v = (d0 < PDIM) ? z[(size_t)n * PDIM + d]
                              : g[(size_t)n * TDIM + (d - PDIM)];
        t[threadIdx.y + i * 8][threadIdx.x] = v;
    }
    __syncthreads();
#pragma unroll
    for (int i = 0; i < 4; i++)
        catT[(size_t)(d0 + threadIdx.y + i * 8) * NR + n0 + threadIdx.x] = t[threadIdx.x][threadIdx.y + i * 8];
}

// =====================================================================
// Proj GEMM + L2 norm (FFMA2 mainloop):
// outT[d][row] = l2norm_row( catT^T @ WT + b )
// Block: 128 rows x 128 out-cols, 256 threads, 8x8 microtile, 24 k-tiles.
// Output-dim pairing: each 64-bit acc holds cols (2m, 2m+1) -> per-scalar
// reduction order identical to the scalar version.
// =====================================================================
__global__ void __launch_bounds__(256, 1) proj_gemm_kernel(
    const float* __restrict__ catT, const float* __restrict__ WT,
    const float* __restrict__ bias, float* __restrict__ outT, int NR)
{
    extern __shared__ float dyn[];
    float* is = dyn;            // [32][128]
    float* ws = dyn + 4096;     // [32][128]
    __shared__ float invs[128];

    const int tid = threadIdx.x;
    const int tx = tid & 15;
    const int ty = tid >> 4;
    const int row0 = blockIdx.x * 128;

    unsigned long long acc2[8][4];
#pragma unroll
    for (int m = 0; m < 4; m++) {
        unsigned long long bp = pack2(bias[tx * 8 + 2 * m], bias[tx * 8 + 2 * m + 1]);
#pragma unroll
        for (int j = 0; j < 8; j++) acc2[j][m] = bp;
    }

    for (int kt = 0; kt < 24; kt++) {
#pragma unroll
        for (int it = 0; it < 4; it++) {
            int idx = tid + it * 256;
            int dd = idx >> 5, c4 = idx & 31;
            *(float4*)&is[dd * 128 + c4 * 4] =
                *(const float4*)&catT[(size_t)(kt * 32 + dd) * NR + row0 + c4 * 4];
            *(float4*)&ws[dd * 128 + c4 * 4] =
                *(const float4*)&WT[(size_t)(kt * 32 + dd) * RDIM + c4 * 4];
        }
        __syncthreads();
#pragma unroll 4
        for (int dd = 0; dd < 32; dd++) {
            float a[8];
            *(float4*)&a[0] = *(float4*)&is[dd * 128 + ty * 8];
            *(float4*)&a[4] = *(float4*)&is[dd * 128 + ty * 8 + 4];
            ulonglong2 bl0 = *(const ulonglong2*)&ws[dd * 128 + tx * 8];
            ulonglong2 bl1 = *(const ulonglong2*)&ws[dd * 128 + tx * 8 + 4];
            unsigned long long b2[4] = { bl0.x, bl0.y, bl1.x, bl1.y };
#pragma unroll
            for (int j = 0; j < 8; j++) {
                unsigned long long a2 = pack2(a[j], a[j]);
#pragma unroll
                for (int m = 0; m < 4; m++) ffma2(acc2[j][m], a2, b2[m]);
            }
        }
        __syncthreads();
    }

    float acc[8][8];
#pragma unroll
    for (int j = 0; j < 8; j++)
#pragma unroll
        for (int m = 0; m < 4; m++)
            unpack2(acc2[j][m], acc[j][2 * m], acc[j][2 * m + 1]);

    // row sum-of-squares reduction across the 16 tx groups
    float* red = dyn;   // [128][16]
#pragma unroll
    for (int j = 0; j < 8; j++) {
        float p = 0.f;
#pragma unroll
        for (int m = 0; m < 8; m++) p += acc[j][m] * acc[j][m];
        red[(ty * 8 + j) * 16 + tx] = p;
    }
    __syncthreads();
    if (tid < 128) {
        float ss = 0.f;
#pragma unroll
        for (int t = 0; t < 16; t++) ss += red[tid * 16 + t];
        invs[tid] = 1.0f / fmaxf(sqrtf(ss), 1e-12f);
    }
    __syncthreads();

    float* os = dyn;    // [128 col][129]
#pragma unroll
    for (int j = 0; j < 8; j++) {
        float iv = invs[ty * 8 + j];
#pragma unroll
        for (int m = 0; m < 8; m++)
            os[(tx * 8 + m) * 129 + ty * 8 + j] = acc[j][m] * iv;
    }
    __syncthreads();
    for (int it = 0; it < 64; it++) {
        int idx = tid + it * 256;
        int col = idx >> 7, r = idx & 127;
        outT[(size_t)col * NR + row0 + r] = os[col * 129 + r];
    }
}

// =====================================================================
// sim = q @ k^T (FFMA2 mainloop).  Block = 128q x 128k, d=128 staged once.
// =====================================================================
__global__ void __launch_bounds__(256, 1) sim_kernel(float* __restrict__ sim)
{
    extern __shared__ float smem[];
    float* qs = smem;            // [128 d][128 q]
    float* ks = smem + 16384;    // [128 d][128 k]

    const int tid = threadIdx.x;
    const int kt = blockIdx.x;
    const int qt = blockIdx.y;

#pragma unroll
    for (int it = 0; it < 16; it++) {
        int idx = tid + it * 256;
        int d = idx >> 5, c4 = idx & 31;
        *(float4*)&qs[d * 128 + c4 * 4] =
            *(const float4*)&g_qT[(size_t)d * BB + qt * 128 + c4 * 4];
        *(float4*)&ks[d * 128 + c4 * 4] =
            *(const float4*)&g_kT[(size_t)d * NN + (size_t)kt * 128 + c4 * 4];
    }
    __syncthreads();

    const int tx = tid & 15;   // k group
    const int ty = tid >> 4;   // q group

    unsigned long long acc2[8][4];
#pragma unroll
    for (int j = 0; j < 8; j++)
#pragma unroll
        for (int m = 0; m < 4; m++) acc2[j][m] = 0ull;

#pragma unroll 4
    for (int d = 0; d < 128; d++) {
        float a[8];
        *(float4*)&a[0] = *(float4*)&qs[d * 128 + ty * 8];
        *(float4*)&a[4] = *(float4*)&qs[d * 128 + ty * 8 + 4];
        ulonglong2 bl0 = *(const ulonglong2*)&ks[d * 128 + tx * 8];
        ulonglong2 bl1 = *(const ulonglong2*)&ks[d * 128 + tx * 8 + 4];
        unsigned long long b2[4] = { bl0.x, bl0.y, bl1.x, bl1.y };
#pragma unroll
        for (int j = 0; j < 8; j++) {
            unsigned long long a2 = pack2(a[j], a[j]);
#pragma unroll
            for (int m = 0; m < 4; m++) ffma2(acc2[j][m], a2, b2[m]);
        }
    }

#pragma unroll
    for (int j = 0; j < 8; j++) {
        float acc[8];
#pragma unroll
        for (int m = 0; m < 4; m++) unpack2(acc2[j][m], acc[2 * m], acc[2 * m + 1]);
        size_t base = (size_t)(qt * 128 + ty * 8 + j) * NN + (size_t)kt * 128 + tx * 8;
        *(float4*)&sim[base]     = make_float4(acc[0], acc[1], acc[2], acc[3]);
        *(float4*)&sim[base + 4] = make_float4(acc[4], acc[5], acc[6], acc[7]);
    }
}

// =====================================================================
// masked top-16 per row (jax tie-break: lower index first)
// =====================================================================
__device__ __forceinline__ void topk_push(float v, int n, float* lv, int* li)
{
    if (v > lv[15] || (v == lv[15] && n < li[15])) {
        float cv = v; int ci = n;
#pragma unroll
        for (int j = 0; j < 16; j++) {
            bool better = (cv > lv[j]) || (cv == lv[j] && ci < li[j]);
            float tv = lv[j]; int ti = li[j];
            if (better) { lv[j] = cv; li[j] = ci; cv = tv; ci = ti; }
        }
    }
}

__global__ void __launch_bounds__(256) topk_kernel(
    const unsigned int* __restrict__ mask, float* __restrict__ out)
{
    __shared__ float sv[4096];
    __shared__ int   si[4096];
    __shared__ float rv[256];
    __shared__ int   ri[256];
    __shared__ int   rp[256];
    __shared__ int   anyv[256];
    __shared__ float wv[16];
    __shared__ int   wi[16];

    const int b = blockIdx.x, tid = threadIdx.x;
    const float4* s4 = (const float4*)(g_sim + (size_t)b * NN);
    const uint4*  m4 = (const uint4*)(mask + (size_t)b * NN);

    float lv[16]; int li[16];
#pragma unroll
    for (int j = 0; j < 16; j++) { lv[j] = -INFINITY; li[j] = 0x7fffffff; }
    unsigned int hv = 0;

    for (int n4 = tid; n4 < NN / 4; n4 += 256) {
        float4 v4 = s4[n4];
        uint4  mm = m4[n4];
        hv |= (mm.x | mm.y | mm.z | mm.w);
        int n = n4 * 4;
        topk_push(mm.x ? v4.x : -1e9f, n + 0, lv, li);
        topk_push(mm.y ? v4.y : -1e9f, n + 1, lv, li);
        topk_push(mm.z ? v4.z : -1e9f, n + 2, lv, li);
        topk_push(mm.w ? v4.w : -1e9f, n + 3, lv, li);
    }
#pragma unroll
    for (int j = 0; j < 16; j++) { sv[tid * 16 + j] = lv[j]; si[tid * 16 + j] = li[j]; }
    anyv[tid] = (hv != 0u);
    __syncthreads();
    for (int s = 128; s > 0; s >>= 1) {
        if (tid < s) anyv[tid] |= anyv[tid + s];
        __syncthreads();
    }

    int p = 0;
    for (int r = 0; r < 16; r++) {
        float v = (p < 16) ? sv[tid * 16 + p] : -INFINITY;
        int   i = (p < 16) ? si[tid * 16 + p] : 0x7fffffff;
        rv[tid] = v; ri[tid] = i; rp[tid] = tid;
        __syncthreads();
        for (int s = 128; s > 0; s >>= 1) {
            if (tid < s) {
                float v2 = rv[tid + s]; int i2 = ri[tid + s];
                if (v2 > rv[tid] || (v2 == rv[tid] && i2 < ri[tid])) {
                    rv[tid] = v2; ri[tid] = i2; rp[tid] = rp[tid + s];
                }
            }
            __syncthreads();
        }
        if (tid == 0) { wv[r] = rv[0]; wi[r] = ri[0]; }
        int owner = rp[0];
        __syncthreads();
        if (tid == owner) p++;
        __syncthreads();
    }

    if (tid < 16) {
        out[OUT_TS + b * 16 + tid] = wv[tid];
        out[OUT_TI + b * 16 + tid] = (float)wi[tid];
        g_topidx[b * 16 + tid] = wi[tid];
    }
    if (tid == 0) g_hasvalid[b] = anyv[0];
}

// =====================================================================
// per-row attention stack
// =====================================================================
__global__ void __launch_bounds__(128) attn_kernel(
    const float* __restrict__ bank_y,
    const float* __restrict__ Ws1, const float* __restrict__ bs1,
    const float* __restrict__ Ws2, const float* __restrict__ bs2,
    const float* __restrict__ Wc1, const float* __restrict__ bc1,
    const float* __restrict__ Wc2, const float* __restrict__ bc2,
    float* __restrict__ out)
{
    __shared__ float y[16][64];
    __shared__ float hbuf[16][128];
    __shared__ float proj[16][128];
    __shared__ float qv[128];
    __shared__ float cmat[128 * 16];
    __shared__ float tred[8 * 16];
    __shared__ float lg[16];
    __shared__ float alpha[16];
    __shared__ int   tix[16];

    const int b = blockIdx.x, tid = threadIdx.x;
    if (tid < 16) tix[tid] = g_topidx[b * 16 + tid];
    qv[tid] = g_qT[(size_t)tid * BB + b];
    __syncthreads();

    for (int e = tid; e < 16 * 64; e += 128)
        y[e >> 6][e & 63] = bank_y[(size_t)tix[e >> 6] * 64 + (e & 63)];
    __syncthreads();

    const int r = tid;
    {
        float4 w[16];
        const float4* W4 = (const float4*)(Ws1 + (size_t)r * 64);
#pragma unroll
        for (int i = 0; i < 16; i++) w[i] = W4[i];
        float bv = bs1[r];
        for (int j = 0; j < 16; j++) {
            float s = bv;
#pragma unroll
            for (int i = 0; i < 16; i++) {
                float4 yy = *(const float4*)&y[j][i * 4];
                s += w[i].x * yy.x + w[i].y * yy.y + w[i].z * yy.z + w[i].w * yy.w;
            }
            hbuf[j][r] = fmaxf(s, 0.f);
        }
    }
    __syncthreads();
    {
        float accp[16];
        float bv = bs2[r];
#pragma unroll
        for (int j = 0; j < 16; j++) accp[j] = bv;
        const float4* W4 = (const float4*)(Ws2 + (size_t)r * 128);
        for (int i = 0; i < 32; i++) {
            float4 w = W4[i];
#pragma unroll
            for (int j = 0; j < 16; j++) {
                float4 hh = *(const float4*)&hbuf[j][i * 4];
                accp[j] += w.x * hh.x + w.y * hh.y + w.z * hh.z + w.w * hh.w;
            }
        }
#pragma unroll
        for (int j = 0; j < 16; j++) proj[j][r] = accp[j];
    }
    __syncthreads();

    {
        float uqr = bc1[r];
        const float4* Wq4 = (const float4*)(Wc1 + (size_t)r * 256);
        for (int i = 0; i < 32; i++) {
            float4 w = Wq4[i];
            float4 qq = *(const float4*)&qv[i * 4];
            uqr += w.x * qq.x + w.y * qq.y + w.z * qq.z + w.w * qq.w;
        }
        float sacc[16];
#pragma unroll
        for (int j = 0; j < 16; j++) sacc[j] = uqr;
        const float4* Wp4 = (const float4*)(Wc1 + (size_t)r * 256 + 128);
        for (int i = 0; i < 32; i++) {
            float4 w = Wp4[i];
#pragma unroll
            for (int j = 0; j < 16; j++) {
                float4 pp = *(const float4*)&proj[j][i * 4];
                sacc[j] += w.x * pp.x + w.y * pp.y + w.z * pp.z + w.w * pp.w;
            }
        }
        float w2r = Wc2[r];
#pragma unroll
        for (int j = 0; j < 16; j++) cmat[r * 16 + j] = tanhf(sacc[j]) * w2r;
    }
    __syncthreads();
    {
        int j = tid & 15, c = tid >> 4;
        float s = 0.f;
        for (int i = 0; i < 16; i++) s += cmat[(c * 16 + i) * 16 + j];
        tred[c * 16 + j] = s;
    }
    __syncthreads();
    if (tid < 16) {
        float s = bc2[0];
        for (int c = 0; c < 8; c++) s += tred[c * 16 + tid];
        lg[tid] = s;
    }
    __syncthreads();
    if (tid == 0) {
        if (g_hasvalid[b]) {
            float mx = lg[0];
            for (int j = 1; j < 16; j++) mx = fmaxf(mx, lg[j]);
            float se = 0.f, ev[16];
            for (int j = 0; j < 16; j++) { ev[j] = expf(lg[j] - mx); se += ev[j]; }
            float isv = 1.0f / se;
            for (int j = 0; j < 16; j++) alpha[j] = ev[j] * isv;
        } else {
            for (int j = 0; j < 16; j++) alpha[j] = 0.f;
        }
    }
    __syncthreads();
    if (tid < 16) out[OUT_AL + b * 16 + tid] = alpha[tid];
    {
        float s = 0.f;
#pragma unroll
        for (int j = 0; j < 16; j++) s += alpha[j] * proj[j][tid];
        g_r[(size_t)b * 128 + tid] = s;
    }
}

// =====================================================================
// z_tilde = has_valid ? relu([z,r] @ Wa^T + ba) : z   (FFMA2, reduction-paired)
// =====================================================================
__global__ void __launch_bounds__(256) aug_kernel(
    const float* __restrict__ zin, const float* __restrict__ Wa,
    const float* __restrict__ ba, float* __restrict__ out)
{
    __shared__ float zr[16 * 640];
    __shared__ int   hv[16];
    const int tid = threadIdx.x, b0 = blockIdx.x * 16;

    for (int e = tid; e < 16 * PDIM; e += 256) {
        int j = e / PDIM, d = e - j * PDIM;
        zr[j * 640 + d] = zin[(size_t)(b0 + j) * PDIM + d];
    }
    for (int e = tid; e < 16 * RDIM; e += 256) {
        int j = e >> 7, d = e & 127;
        zr[j * 640 + PDIM + d] = g_r[(size_t)(b0 + j) * RDIM + d];
    }
    if (tid < 16) hv[tid] = g_hasvalid[b0 + tid];
    __syncthreads();

    for (int half = 0; half < 2; half++) {
        int o = tid + half * 256;
        unsigned long long acc2[16];
        float bv = ba[o];
#pragma unroll
        for (int j = 0; j < 16; j++) acc2[j] = pack2(bv, 0.f);
        const ulonglong2* W2 = (const ulonglong2*)(Wa + (size_t)o * 640);
        for (int i = 0; i < 160; i++) {
            ulonglong2 w = W2[i];
#pragma unroll
            for (int j = 0; j < 16; j++) {
                ulonglong2 zz = *(const ulonglong2*)&zr[j * 640 + i * 4];
                ffma2(acc2[j], w.x, zz.x);
                ffma2(acc2[j], w.y, zz.y);
            }
        }
#pragma unroll
        for (int j = 0; j < 16; j++) {
            float lo, hi;
            unpack2(acc2[j], lo, hi);
            float v = hv[j] ? fmaxf(lo + hi, 0.f) : zr[j * 640 + o];
            out[(size_t)(b0 + j) * PDIM + o] = v;
        }
    }
}

// =====================================================================
extern "C" void kernel_launch(void* const* d_in, const int* in_sizes, int n_in,
                              void* d_out, int out_size)
{
    const float* z_i    = (const float*)d_in[0];
    const float* g_i    = (const float*)d_in[1];
    const float* bank_z = (const float*)d_in[2];
    const float* bank_g = (const float*)d_in[3];
    const float* bank_y = (const float*)d_in[4];
    const unsigned int* vmask = (const unsigned int*)d_in[5];
    const float* Wq  = (const float*)d_in[6];
    const float* bq  = (const float*)d_in[7];
    const float* Wk  = (const float*)d_in[8];
    const float* bk  = (const float*)d_in[9];
    const float* Ws1 = (const float*)d_in[10];
    const float* bs1 = (const float*)d_in[11];
    const float* Ws2 = (const float*)d_in[12];
    const float* bs2 = (const float*)d_in[13];
    const float* Wc1 = (const float*)d_in[14];
    const float* bc1 = (const float*)d_in[15];
    const float* Wc2 = (const float*)d_in[16];
    const float* bc2 = (const float*)d_in[17];
    const float* Wa  = (const float*)d_in[18];
    const float* ba  = (const float*)d_in[19];
    float* out = (float*)d_out;

    float* p_bcatT; cudaGetSymbolAddress((void**)&p_bcatT, g_bcatT);
    float* p_qcatT; cudaGetSymbolAddress((void**)&p_qcatT, g_qcatT);
    float* p_WqT;   cudaGetSymbolAddress((void**)&p_WqT, g_WqT);
    float* p_WkT;   cudaGetSymbolAddress((void**)&p_WkT, g_WkT);
    float* p_qT;    cudaGetSymbolAddress((void**)&p_qT, g_qT);
    float* p_kT;    cudaGetSymbolAddress((void**)&p_kT, g_kT);
    float* p_sim;   cudaGetSymbolAddress((void**)&p_sim, g_sim);

    const int smemProj = 16512 * 4;
    const int smemSim  = 32768 * 4;

    cudaFuncSetAttribute(proj_gemm_kernel, cudaFuncAttributeMaxDynamicSharedMemorySize, smemProj);
    cudaFuncSetAttribute(sim_kernel, cudaFuncAttributeMaxDynamicSharedMemorySize, smemSim);

    wT_kernel<<<dim3(24, 4, 2), dim3(32, 8)>>>(Wq, Wk);
    catT_kernel<<<dim3(NN / 32, 24), dim3(32, 8)>>>(bank_z, bank_g, p_bcatT, NN);
    catT_kernel<<<dim3(BB / 32, 24), dim3(32, 8)>>>(z_i, g_i, p_qcatT, BB);

    proj_gemm_kernel<<<BB / 128, 256, smemProj>>>(p_qcatT, p_WqT, bq, p_qT, BB);
    proj_gemm_kernel<<<NN / 128, 256, smemProj>>>(p_bcatT, p_WkT, bk, p_kT, NN);

    sim_kernel<<<dim3(NN / 128, BB / 128), 256, smemSim>>>(p_sim);
    topk_kernel<<<BB, 256>>>(vmask, out);
    attn_kernel<<<BB, 128>>>(bank_y, Ws1, bs1, Ws2, bs2, Wc1, bc1, Wc2, bc2, out);
    aug_kernel<<<BB / 16, 256>>>(z_i, Wa, ba, out);
}

// round 8
// speedup vs baseline: 1.7069x; 1.0452x over previous
#include <cuda_runtime.h>
#include <cuda_bf16.h>
#include <cstdint>
#include <math.h>

#define BB   2048
#define NN   65536
#define PDIM 512
#define TDIM 256
#define CDIM 768
#define HDIM 64
#define RDIM 128
#define KK   16

// ---------------- scratch (device globals; no allocations) ----------------
__device__ float g_bcatT[CDIM * NN];          // bank concat, d-major
__device__ float g_qcatT[CDIM * BB];          // query concat, d-major
__device__ float g_WqT[CDIM * RDIM];
__device__ float g_WkT[CDIM * RDIM];
__device__ float g_qT[RDIM * BB];             // normalized queries, d-major (attn)
__device__ __nv_bfloat16 g_qs[3][BB * RDIM];  // q bf16x3 splits, row-major
__device__ __nv_bfloat16 g_ks[3][(size_t)NN * RDIM]; // k bf16x3 splits, row-major
__device__ float g_sim[(size_t)BB * NN];      // similarity
__device__ int   g_topidx[BB * KK];
__device__ float g_r[BB * RDIM];
__device__ int   g_hasvalid[BB];

// output layout (floats)
#define OUT_TS (BB * PDIM)
#define OUT_TI (OUT_TS + BB * KK)
#define OUT_AL (OUT_TI + BB * KK)

// ---------------- bf16 split helpers ----------------
__device__ __forceinline__ unsigned short bf16bits(float v) {
    __nv_bfloat16 b = __float2bfloat16(v);
    return *reinterpret_cast<unsigned short*>(&b);
}
__device__ __forceinline__ float bf16f(unsigned short u) {
    __nv_bfloat16 b = *reinterpret_cast<__nv_bfloat16*>(&u);
    return __bfloat162float(b);
}
__device__ __forceinline__ uint4 pack8(const unsigned short* u) {
    uint4 r;
    r.x = (uint32_t)u[0] | ((uint32_t)u[1] << 16);
    r.y = (uint32_t)u[2] | ((uint32_t)u[3] << 16);
    r.z = (uint32_t)u[4] | ((uint32_t)u[5] << 16);
    r.w = (uint32_t)u[6] | ((uint32_t)u[7] << 16);
    return r;
}
__device__ __forceinline__ uint32_t smem_u32(const void* p) {
    uint32_t a;
    asm("{ .reg .u64 t; cvta.to.shared.u64 t, %1; cvt.u32.u64 %0, t; }" : "=r"(a) : "l"(p));
    return a;
}

// =====================================================================
// Prep A: transpose Wq/Wk [128][768] -> WT [768][128]
// =====================================================================
__global__ void wT_kernel(const float* __restrict__ Wq, const float* __restrict__ Wk)
{
    __shared__ float t[32][33];
    const float* src = blockIdx.z ? Wk : Wq;
    float* dst = blockIdx.z ? g_WkT : g_WqT;
    int c0 = blockIdx.x * 32;
    int r0 = blockIdx.y * 32;
#pragma unroll
    for (int i = 0; i < 4; i++)
        t[threadIdx.y + i * 8][threadIdx.x] = src[(size_t)(r0 + threadIdx.y + i * 8) * CDIM + c0 + threadIdx.x];
    __syncthreads();
#pragma unroll
    for (int i = 0; i < 4; i++)
        dst[(size_t)(c0 + threadIdx.y + i * 8) * RDIM + r0 + threadIdx.x] = t[threadIdx.x][threadIdx.y + i * 8];
}

// =====================================================================
// Prep B: concat+transpose  (rows x [z|g])  ->  catT [768][NR]
// =====================================================================
__global__ void catT_kernel(const float* __restrict__ z, const float* __restrict__ g,
                            float* __restrict__ catT, int NR)
{
    __shared__ float t[32][33];
    int n0 = blockIdx.x * 32;
    int d0 = blockIdx.y * 32;
#pragma unroll
    for (int i = 0; i < 4; i++) {
        int n = n0 + threadIdx.y + i * 8;
        int d = d0 + threadIdx.x;
        float v = (d0 < PDIM) ? z[(size_t)n * PDIM + d]
                              : g[(size_t)n * TDIM + (d - PDIM)];
        t[threadIdx.y + i * 8][threadIdx.x] = v;
    }
    __syncthreads();
#pragma unroll
    for (int i = 0; i < 4; i++)
        catT[(size_t)(d0 + threadIdx.y + i * 8) * NR + n0 + threadIdx.x] = t[threadIdx.x][threadIdx.y + i * 8];
}

// =====================================================================
// Proj GEMM + L2 norm (scalar).  Emits bf16x3 splits (row-major) and
// optionally fp32 d-major outT (queries, for attn kernel).
// =====================================================================
__global__ void __launch_bounds__(256, 1) proj_gemm_kernel(
    const float* __restrict__ catT, const float* __restrict__ WT,
    const float* __restrict__ bias, float* __restrict__ outT,
    __nv_bfloat16* __restrict__ s0, __nv_bfloat16* __restrict__ s1,
    __nv_bfloat16* __restrict__ s2, int NR)
{
    extern __shared__ float dyn[];
    float* is = dyn;            // [32][128]
    float* ws = dyn + 4096;     // [32][128]
    __shared__ float invs[128];

    const int tid = threadIdx.x;
    const int tx = tid & 15;
    const int ty = tid >> 4;
    const int row0 = blockIdx.x * 128;

    float acc[8][8];
#pragma unroll
    for (int m = 0; m < 8; m++) {
        float bv = bias[tx * 8 + m];
#pragma unroll
        for (int j = 0; j < 8; j++) acc[j][m] = bv;
    }

    for (int kt = 0; kt < 24; kt++) {
#pragma unroll
        for (int it = 0; it < 4; it++) {
            int idx = tid + it * 256;
            int dd = idx >> 5, c4 = idx & 31;
            *(float4*)&is[dd * 128 + c4 * 4] =
                *(const float4*)&catT[(size_t)(kt * 32 + dd) * NR + row0 + c4 * 4];
            *(float4*)&ws[dd * 128 + c4 * 4] =
                *(const float4*)&WT[(size_t)(kt * 32 + dd) * RDIM + c4 * 4];
        }
        __syncthreads();
#pragma unroll 4
        for (int dd = 0; dd < 32; dd++) {
            float a[8], b[8];
            *(float4*)&a[0] = *(float4*)&is[dd * 128 + ty * 8];
            *(float4*)&a[4] = *(float4*)&is[dd * 128 + ty * 8 + 4];
            *(float4*)&b[0] = *(float4*)&ws[dd * 128 + tx * 8];
            *(float4*)&b[4] = *(float4*)&ws[dd * 128 + tx * 8 + 4];
#pragma unroll
            for (int j = 0; j < 8; j++)
#pragma unroll
                for (int m = 0; m < 8; m++)
                    acc[j][m] += a[j] * b[m];
        }
        __syncthreads();
    }

    // row sum-of-squares reduction across the 16 tx groups
    float* red = dyn;   // [128][16]
#pragma unroll
    for (int j = 0; j < 8; j++) {
        float p = 0.f;
#pragma unroll
        for (int m = 0; m < 8; m++) p += acc[j][m] * acc[j][m];
        red[(ty * 8 + j) * 16 + tx] = p;
    }
    __syncthreads();
    if (tid < 128) {
        float ss = 0.f;
#pragma unroll
        for (int t = 0; t < 16; t++) ss += red[tid * 16 + t];
        invs[tid] = 1.0f / fmaxf(sqrtf(ss), 1e-12f);
    }
    __syncthreads();

    // bf16x3 split emit (row-major [row][128])
#pragma unroll
    for (int j = 0; j < 8; j++) {
        float iv = invs[ty * 8 + j];
        int row = row0 + ty * 8 + j;
        unsigned short u0[8], u1[8], u2[8];
#pragma unroll
        for (int m = 0; m < 8; m++) {
            float v = acc[j][m] * iv;
            u0[m] = bf16bits(v);
            float r1 = v - bf16f(u0[m]);
            u1[m] = bf16bits(r1);
            float r2 = r1 - bf16f(u1[m]);
            u2[m] = bf16bits(r2);
        }
        size_t base = (size_t)row * RDIM + tx * 8;
        *(uint4*)&s0[base] = pack8(u0);
        *(uint4*)&s1[base] = pack8(u1);
        *(uint4*)&s2[base] = pack8(u2);
    }

    if (outT) {
        __syncthreads();
        float* os = dyn;    // [128 col][129]
#pragma unroll
        for (int j = 0; j < 8; j++) {
            float iv = invs[ty * 8 + j];
#pragma unroll
            for (int m = 0; m < 8; m++)
                os[(tx * 8 + m) * 129 + ty * 8 + j] = acc[j][m] * iv;
        }
        __syncthreads();
        for (int it = 0; it < 64; it++) {
            int idx = tid + it * 256;
            int col = idx >> 7, r = idx & 127;
            outT[(size_t)col * NR + row0 + r] = os[col * 129 + r];
        }
    }
}

// =====================================================================
// sim = q @ k^T via warp-level mma.sync (bf16x3, 6 products, fp32 acc).
// CTA: 128q x 128k, 8 warps, warp w owns m-strip [w*16, w*16+16).
// smem: A split tile 32KB + B split tile 32KB, XOR-swizzled 16B units.
// =====================================================================
__device__ __forceinline__ void load_tile_bf16(char* dst, const __nv_bfloat16* src, int tid)
{
    const uint4* s4 = (const uint4*)src;   // 16B units, row-major [128][128]bf16
#pragma unroll
    for (int it = 0; it < 8; it++) {
        int u = tid + it * 256;            // 0..2047
        int r = u >> 4, c = u & 15;
        *(uint4*)(dst + r * 256 + ((c ^ (r & 7)) << 4)) = s4[u];
    }
}

__global__ void __launch_bounds__(256, 2) sim_mma_kernel(float* __restrict__ sim)
{
    extern __shared__ __align__(16) char smem[];
    char* As = smem;             // 32KB: [128 m][128 bf16] swizzled
    char* Bs = smem + 32768;     // 32KB: [128 n][128 bf16] swizzled

    const int tid = threadIdx.x;
    const int w = tid >> 5, lane = tid & 31;
    const int qrow0 = blockIdx.y * 128;
    const int krow0 = blockIdx.x * 128;

    const uint32_t sbA = smem_u32(As);
    const uint32_t sbB = smem_u32(Bs);

    // A-fragment lane addressing (fixed row per lane)
    const int ar = w * 16 + (lane & 7) + ((lane >> 3) & 1) * 8;
    const int acu_half = (lane >> 4);           // 0/1
    const uint32_t aBase = sbA + ar * 256;
    const int asw = ar & 7;
    // B-fragment lane addressing
    const int brl = (lane & 7) + ((lane >> 4) ? 8 : 0);   // row within n16 block
    const int bcu_half = (lane >> 3) & 1;

    float acc[16][4];
#pragma unroll
    for (int i = 0; i < 16; i++)
#pragma unroll
        for (int j = 0; j < 4; j++) acc[i][j] = 0.f;

    const int PA[6] = {0, 1, 1, 0, 0, 2};
    const int PB[6] = {0, 0, 1, 1, 2, 0};

#pragma unroll
    for (int p = 0; p < 6; p++) {
        bool la = (p == 0) || (PA[p] != PA[p - 1]);
        bool lb = (p == 0) || (PB[p] != PB[p - 1]);
        __syncthreads();
        if (la) load_tile_bf16(As, &g_qs[PA[p]][(size_t)qrow0 * RDIM], tid);
        if (lb) load_tile_bf16(Bs, &g_ks[PB[p]][(size_t)krow0 * RDIM], tid);
        __syncthreads();

#pragma unroll
        for (int ks = 0; ks < 8; ks++) {
            uint32_t a0, a1, a2, a3;
            {
                int cu = ks * 2 + acu_half;
                uint32_t aaddr = aBase + ((cu ^ asw) << 4);
                asm volatile("ldmatrix.sync.aligned.m8n8.x4.shared.b16 {%0,%1,%2,%3}, [%4];"
                             : "=r"(a0), "=r"(a1), "=r"(a2), "=r"(a3) : "r"(aaddr));
            }
#pragma unroll
            for (int nt = 0; nt < 8; nt++) {
                uint32_t b0, b1, b2, b3;
                int br = nt * 16 + brl;
                int cu = ks * 2 + bcu_half;
                uint32_t baddr = sbB + br * 256 + ((cu ^ (br & 7)) << 4);
                asm volatile("ldmatrix.sync.aligned.m8n8.x4.shared.b16 {%0,%1,%2,%3}, [%4];"
                             : "=r"(b0), "=r"(b1), "=r"(b2), "=r"(b3) : "r"(baddr));
                asm volatile(
                    "mma.sync.aligned.m16n8k16.row.col.f32.bf16.bf16.f32 "
                    "{%0,%1,%2,%3}, {%4,%5,%6,%7}, {%8,%9}, {%0,%1,%2,%3};"
                    : "+f"(acc[nt * 2][0]), "+f"(acc[nt * 2][1]),
                      "+f"(acc[nt * 2][2]), "+f"(acc[nt * 2][3])
                    : "r"(a0), "r"(a1), "r"(a2), "r"(a3), "r"(b0), "r"(b1));
                asm volatile(
                    "mma.sync.aligned.m16n8k16.row.col.f32.bf16.bf16.f32 "
                    "{%0,%1,%2,%3}, {%4,%5,%6,%7}, {%8,%9}, {%0,%1,%2,%3};"
                    : "+f"(acc[nt * 2 + 1][0]), "+f"(acc[nt * 2 + 1][1]),
                      "+f"(acc[nt * 2 + 1][2]), "+f"(acc[nt * 2 + 1][3])
                    : "r"(a0), "r"(a1), "r"(a2), "r"(a3), "r"(b2), "r"(b3));
            }
        }
    }

    // store: thread t covers rows (w*16 + t/4) and (+8), cols nt*8 + (t%4)*2
    const int t4 = lane >> 2, tp = lane & 3;
    const size_t row_a = (size_t)(qrow0 + w * 16 + t4) * NN + krow0;
    const size_t row_b = (size_t)(qrow0 + w * 16 + t4 + 8) * NN + krow0;
#pragma unroll
    for (int nt = 0; nt < 16; nt++) {
        int col = nt * 8 + tp * 2;
        *(float2*)&sim[row_a + col] = make_float2(acc[nt][0], acc[nt][1]);
        *(float2*)&sim[row_b + col] = make_float2(acc[nt][2], acc[nt][3]);
    }
}

// =====================================================================
// masked top-16 per row (jax tie-break: lower index first)
// =====================================================================
__device__ __forceinline__ void topk_push(float v, int n, float* lv, int* li)
{
    if (v > lv[15] || (v == lv[15] && n < li[15])) {
        float cv = v; int ci = n;
#pragma unroll
        for (int j = 0; j < 16; j++) {
            bool better = (cv > lv[j]) || (cv == lv[j] && ci < li[j]);
            float tv = lv[j]; int ti = li[j];
            if (better) { lv[j] = cv; li[j] = ci; cv = tv; ci = ti; }
        }
    }
}

__global__ void __launch_bounds__(256) topk_kernel(
    const unsigned int* __restrict__ mask, float* __restrict__ out)
{
    __shared__ float sv[4096];
    __shared__ int   si[4096];
    __shared__ float rv[256];
    __shared__ int   ri[256];
    __shared__ int   rp[256];
    __shared__ int   anyv[256];
    __shared__ float wv[16];
    __shared__ int   wi[16];

    const int b = blockIdx.x, tid = threadIdx.x;
    const float4* s4 = (const float4*)(g_sim + (size_t)b * NN);
    const uint4*  m4 = (const uint4*)(mask + (size_t)b * NN);

    float lv[16]; int li[16];
#pragma unroll
    for (int j = 0; j < 16; j++) { lv[j] = -INFINITY; li[j] = 0x7fffffff; }
    unsigned int hv = 0;

    for (int n4 = tid; n4 < NN / 4; n4 += 256) {
        float4 v4 = s4[n4];
        uint4  mm = m4[n4];
        hv |= (mm.x | mm.y | mm.z | mm.w);
        int n = n4 * 4;
        topk_push(mm.x ? v4.x : -1e9f, n + 0, lv, li);
        topk_push(mm.y ? v4.y : -1e9f, n + 1, lv, li);
        topk_push(mm.z ? v4.z : -1e9f, n + 2, lv, li);
        topk_push(mm.w ? v4.w : -1e9f, n + 3, lv, li);
    }
#pragma unroll
    for (int j = 0; j < 16; j++) { sv[tid * 16 + j] = lv[j]; si[tid * 16 + j] = li[j]; }
    anyv[tid] = (hv != 0u);
    __syncthreads();
    for (int s = 128; s > 0; s >>= 1) {
        if (tid < s) anyv[tid] |= anyv[tid + s];
        __syncthreads();
    }

    int p = 0;
    for (int r = 0; r < 16; r++) {
        float v = (p < 16) ? sv[tid * 16 + p] : -INFINITY;
        int   i = (p < 16) ? si[tid * 16 + p] : 0x7fffffff;
        rv[tid] = v; ri[tid] = i; rp[tid] = tid;
        __syncthreads();
        for (int s = 128; s > 0; s >>= 1) {
            if (tid < s) {
                float v2 = rv[tid + s]; int i2 = ri[tid + s];
                if (v2 > rv[tid] || (v2 == rv[tid] && i2 < ri[tid])) {
                    rv[tid] = v2; ri[tid] = i2; rp[tid] = rp[tid + s];
                }
            }
            __syncthreads();
        }
        if (tid == 0) { wv[r] = rv[0]; wi[r] = ri[0]; }
        int owner = rp[0];
        __syncthreads();
        if (tid == owner) p++;
        __syncthreads();
    }

    if (tid < 16) {
        out[OUT_TS + b * 16 + tid] = wv[tid];
        out[OUT_TI + b * 16 + tid] = (float)wi[tid];
        g_topidx[b * 16 + tid] = wi[tid];
    }
    if (tid == 0) g_hasvalid[b] = anyv[0];
}

// =====================================================================
// per-row attention stack
// =====================================================================
__global__ void __launch_bounds__(128) attn_kernel(
    const float* __restrict__ bank_y,
    const float* __restrict__ Ws1, const float* __restrict__ bs1,
    const float* __restrict__ Ws2, const float* __restrict__ bs2,
    const float* __restrict__ Wc1, const float* __restrict__ bc1,
    const float* __restrict__ Wc2, const float* __restrict__ bc2,
    float* __restrict__ out)
{
    __shared__ float y[16][64];
    __shared__ float hbuf[16][128];
    __shared__ float proj[16][128];
    __shared__ float qv[128];
    __shared__ float cmat[128 * 16];
    __shared__ float tred[8 * 16];
    __shared__ float lg[16];
    __shared__ float alpha[16];
    __shared__ int   tix[16];

    const int b = blockIdx.x, tid = threadIdx.x;
    if (tid < 16) tix[tid] = g_topidx[b * 16 + tid];
    qv[tid] = g_qT[(size_t)tid * BB + b];
    __syncthreads();

    for (int e = tid; e < 16 * 64; e += 128)
        y[e >> 6][e & 63] = bank_y[(size_t)tix[e >> 6] * 64 + (e & 63)];
    __syncthreads();

    const int r = tid;
    {
        float4 w[16];
        const float4* W4 = (const float4*)(Ws1 + (size_t)r * 64);
#pragma unroll
        for (int i = 0; i < 16; i++) w[i] = W4[i];
        float bv = bs1[r];
        for (int j = 0; j < 16; j++) {
            float s = bv;
#pragma unroll
            for (int i = 0; i < 16; i++) {
                float4 yy = *(const float4*)&y[j][i * 4];
                s += w[i].x * yy.x + w[i].y * yy.y + w[i].z * yy.z + w[i].w * yy.w;
            }
            hbuf[j][r] = fmaxf(s, 0.f);
        }
    }
    __syncthreads();
    {
        float accp[16];
        float bv = bs2[r];
#pragma unroll
        for (int j = 0; j < 16; j++) accp[j] = bv;
        const float4* W4 = (const float4*)(Ws2 + (size_t)r * 128);
        for (int i = 0; i < 32; i++) {
            float4 w = W4[i];
#pragma unroll
            for (int j = 0; j < 16; j++) {
                float4 hh = *(const float4*)&hbuf[j][i * 4];
                accp[j] += w.x * hh.x + w.y * hh.y + w.z * hh.z + w.w * hh.w;
            }
        }
#pragma unroll
        for (int j = 0; j < 16; j++) proj[j][r] = accp[j];
    }
    __syncthreads();

    {
        float uqr = bc1[r];
        const float4* Wq4 = (const float4*)(Wc1 + (size_t)r * 256);
        for (int i = 0; i < 32; i++) {
            float4 w = Wq4[i];
            float4 qq = *(const float4*)&qv[i * 4];
            uqr += w.x * qq.x + w.y * qq.y + w.z * qq.z + w.w * qq.w;
        }
        float sacc[16];
#pragma unroll
        for (int j = 0; j < 16; j++) sacc[j] = uqr;
        const float4* Wp4 = (const float4*)(Wc1 + (size_t)r * 256 + 128);
        for (int i = 0; i < 32; i++) {
            float4 w = Wp4[i];
#pragma unroll
            for (int j = 0; j < 16; j++) {
                float4 pp = *(const float4*)&proj[j][i * 4];
                sacc[j] += w.x * pp.x + w.y * pp.y + w.z * pp.z + w.w * pp.w;
            }
        }
        float w2r = Wc2[r];
#pragma unroll
        for (int j = 0; j < 16; j++) cmat[r * 16 + j] = tanhf(sacc[j]) * w2r;
    }
    __syncthreads();
    {
        int j = tid & 15, c = tid >> 4;
        float s = 0.f;
        for (int i = 0; i < 16; i++) s += cmat[(c * 16 + i) * 16 + j];
        tred[c * 16 + j] = s;
    }
    __syncthreads();
    if (tid < 16) {
        float s = bc2[0];
        for (int c = 0; c < 8; c++) s += tred[c * 16 + tid];
        lg[tid] = s;
    }
    __syncthreads();
    if (tid == 0) {
        if (g_hasvalid[b]) {
            float mx = lg[0];
            for (int j = 1; j < 16; j++) mx = fmaxf(mx, lg[j]);
            float se = 0.f, ev[16];
            for (int j = 0; j < 16; j++) { ev[j] = expf(lg[j] - mx); se += ev[j]; }
            float isv = 1.0f / se;
            for (int j = 0; j < 16; j++) alpha[j] = ev[j] * isv;
        } else {
            for (int j = 0; j < 16; j++) alpha[j] = 0.f;
        }
    }
    __syncthreads();
    if (tid < 16) out[OUT_AL + b * 16 + tid] = alpha[tid];
    {
        float s = 0.f;
#pragma unroll
        for (int j = 0; j < 16; j++) s += alpha[j] * proj[j][tid];
        g_r[(size_t)b * 128 + tid] = s;
    }
}

// =====================================================================
// z_tilde = has_valid ? relu([z,r] @ Wa^T + ba) : z
// =====================================================================
__global__ void __launch_bounds__(256) aug_kernel(
    const float* __restrict__ zin, const float* __restrict__ Wa,
    const float* __restrict__ ba, float* __restrict__ out)
{
    __shared__ float zr[16 * 640];
    __shared__ int   hv[16];
    const int tid = threadIdx.x, b0 = blockIdx.x * 16;

    for (int e = tid; e < 16 * PDIM; e += 256) {
        int j = e / PDIM, d = e - j * PDIM;
        zr[j * 640 + d] = zin[(size_t)(b0 + j) * PDIM + d];
    }
    for (int e = tid; e < 16 * RDIM; e += 256) {
        int j = e >> 7, d = e & 127;
        zr[j * 640 + PDIM + d] = g_r[(size_t)(b0 + j) * RDIM + d];
    }
    if (tid < 16) hv[tid] = g_hasvalid[b0 + tid];
    __syncthreads();

    for (int half = 0; half < 2; half++) {
        int o = tid + half * 256;
        float acc[16];
        float bv = ba[o];
#pragma unroll
        for (int j = 0; j < 16; j++) acc[j] = bv;
        const float4* W4 = (const float4*)(Wa + (size_t)o * 640);
        for (int i = 0; i < 160; i++) {
            float4 w = W4[i];
#pragma unroll
            for (int j = 0; j < 16; j++) {
                float4 zz = *(const float4*)&zr[j * 640 + i * 4];
                acc[j] += w.x * zz.x + w.y * zz.y + w.z * zz.z + w.w * zz.w;
            }
        }
#pragma unroll
        for (int j = 0; j < 16; j++) {
            float v = hv[j] ? fmaxf(acc[j], 0.f) : zr[j * 640 + o];
            out[(size_t)(b0 + j) * PDIM + o] = v;
        }
    }
}

// =====================================================================
extern "C" void kernel_launch(void* const* d_in, const int* in_sizes, int n_in,
                              void* d_out, int out_size)
{
    const float* z_i    = (const float*)d_in[0];
    const float* g_i    = (const float*)d_in[1];
    const float* bank_z = (const float*)d_in[2];
    const float* bank_g = (const float*)d_in[3];
    const float* bank_y = (const float*)d_in[4];
    const unsigned int* vmask = (const unsigned int*)d_in[5];
    const float* Wq  = (const float*)d_in[6];
    const float* bq  = (const float*)d_in[7];
    const float* Wk  = (const float*)d_in[8];
    const float* bk  = (const float*)d_in[9];
    const float* Ws1 = (const float*)d_in[10];
    const float* bs1 = (const float*)d_in[11];
    const float* Ws2 = (const float*)d_in[12];
    const float* bs2 = (const float*)d_in[13];
    const float* Wc1 = (const float*)d_in[14];
    const float* bc1 = (const float*)d_in[15];
    const float* Wc2 = (const float*)d_in[16];
    const float* bc2 = (const float*)d_in[17];
    const float* Wa  = (const float*)d_in[18];
    const float* ba  = (const float*)d_in[19];
    float* out = (float*)d_out;

    float* p_bcatT; cudaGetSymbolAddress((void**)&p_bcatT, g_bcatT);
    float* p_qcatT; cudaGetSymbolAddress((void**)&p_qcatT, g_qcatT);
    float* p_WqT;   cudaGetSymbolAddress((void**)&p_WqT, g_WqT);
    float* p_WkT;   cudaGetSymbolAddress((void**)&p_WkT, g_WkT);
    float* p_qT;    cudaGetSymbolAddress((void**)&p_qT, g_qT);
    float* p_sim;   cudaGetSymbolAddress((void**)&p_sim, g_sim);
    __nv_bfloat16* p_qs; cudaGetSymbolAddress((void**)&p_qs, g_qs);
    __nv_bfloat16* p_ks; cudaGetSymbolAddress((void**)&p_ks, g_ks);

    const int smemProj = 16512 * 4;
    const int smemSim  = 65536;

    cudaFuncSetAttribute(proj_gemm_kernel, cudaFuncAttributeMaxDynamicSharedMemorySize, smemProj);
    cudaFuncSetAttribute(sim_mma_kernel, cudaFuncAttributeMaxDynamicSharedMemorySize, smemSim);

    wT_kernel<<<dim3(24, 4, 2), dim3(32, 8)>>>(Wq, Wk);
    catT_kernel<<<dim3(NN / 32, 24), dim3(32, 8)>>>(bank_z, bank_g, p_bcatT, NN);
    catT_kernel<<<dim3(BB / 32, 24), dim3(32, 8)>>>(z_i, g_i, p_qcatT, BB);

    proj_gemm_kernel<<<BB / 128, 256, smemProj>>>(
        p_qcatT, p_WqT, bq, p_qT,
        p_qs, p_qs + (size_t)BB * RDIM, p_qs + 2 * (size_t)BB * RDIM, BB);
    proj_gemm_kernel<<<NN / 128, 256, smemProj>>>(
        p_bcatT, p_WkT, bk, (float*)nullptr,
        p_ks, p_ks + (size_t)NN * RDIM, p_ks + 2 * (size_t)NN * RDIM, NN);

    sim_mma_kernel<<<dim3(NN / 128, BB / 128), 256, smemSim>>>(p_sim);
    topk_kernel<<<BB, 256>>>(vmask, out);
    attn_kernel<<<BB, 128>>>(bank_y, Ws1, bs1, Ws2, bs2, Wc1, bc1, Wc2, bc2, out);
    aug_kernel<<<BB / 16, 256>>>(z_i, Wa, ba, out);
}